// round 4
// baseline (speedup 1.0000x reference)
#include <cuda_runtime.h>

// ---------------------------------------------------------------------------
// Problem constants (fixed shapes from setup_inputs)
//   B=4, C=256, levels: 16x16 -> 32x32 -> 64x64 -> 128x128, dg=8, Cpg=32
// ---------------------------------------------------------------------------
#define NB 4

// ------------------------- static scratch buffers --------------------------
static __device__ float g_up5 [4u * 256u * 32u * 32u];    //  4 MB
static __device__ float g_off5[4u * 256u * 32u * 32u];    //  4 MB
static __device__ float g_om5 [4u * 216u * 32u * 32u];    //  3.4 MB
static __device__ float g_col [4u * 2304u * 64u * 64u];   // 151 MB (shared by both DCN levels)
static __device__ float g_al5 [4u * 256u * 32u * 32u];    //  4 MB
static __device__ float g_c1b [4u * 256u * 32u * 32u];    //  4 MB
static __device__ float g_up4 [4u * 256u * 64u * 64u];    // 16 MB
static __device__ float g_off4[4u * 256u * 64u * 64u];    // 16 MB
static __device__ float g_om4 [4u * 216u * 64u * 64u];    // 13.5 MB
static __device__ float g_al4 [4u * 256u * 64u * 64u];    // 16 MB
static __device__ float g_f2  [4u * 512u * 128u * 128u];  // 128 MB
static __device__ float g_mm  [4u * 2u * 128u * 128u];    //  0.5 MB
static __device__ float g_sab [4u * 128u * 128u];         //  0.25 MB
static __device__ float g_y   [4u * 256u * 128u * 128u];  // 64 MB
static __device__ float g_st  [256];                      // per (b,group): mean, rstd

// ---------------------------------------------------------------------------
// Bilinear 2x upsample, half-pixel centers, clamp-to-edge.
// Matches jax.image.resize('bilinear') for exact 2x upsampling.
// Dual source: channel c < Csplit reads src0, else src1 (fuses concat+resize).
// ---------------------------------------------------------------------------
__global__ __launch_bounds__(256)
void upsample2x_kernel(const float* __restrict__ src0,
                       const float* __restrict__ src1,
                       int Csplit, int C, int Hin, int Win,
                       float* __restrict__ dst)
{
    const int Hout = Hin * 2, Wout = Win * 2;
    const long total = (long)NB * C * Hout * Wout;
    long idx = (long)blockIdx.x * blockDim.x + threadIdx.x;
    if (idx >= total) return;
    int x = (int)(idx % Wout);
    int y = (int)((idx / Wout) % Hout);
    int c = (int)((idx / ((long)Wout * Hout)) % C);
    int b = (int)(idx / ((long)Wout * Hout * C));

    float sy = y * 0.5f - 0.25f;
    float sx = x * 0.5f - 0.25f;
    float y0f = floorf(sy), x0f = floorf(sx);
    float fy = sy - y0f, fx = sx - x0f;
    int y0 = (int)y0f, x0 = (int)x0f;
    int y0c = min(max(y0, 0), Hin - 1);
    int y1c = min(max(y0 + 1, 0), Hin - 1);
    int x0c = min(max(x0, 0), Win - 1);
    int x1c = min(max(x0 + 1, 0), Win - 1);

    const float* s = (c < Csplit)
        ? src0 + (size_t)(b * Csplit + c) * Hin * Win
        : src1 + (size_t)(b * (C - Csplit) + (c - Csplit)) * Hin * Win;

    float v00 = s[y0c * Win + x0c];
    float v01 = s[y0c * Win + x1c];
    float v10 = s[y1c * Win + x0c];
    float v11 = s[y1c * Win + x1c];
    dst[idx] = (1.f - fy) * ((1.f - fx) * v00 + fx * v01)
             +         fy * ((1.f - fx) * v10 + fx * v11);
}

// ---------------------------------------------------------------------------
// Generic fp32 GEMM: out[b, m, p] = act( sum_k W[m,k] * X(b,k,p) + bias[m] )
// X loader modes:
//   0: plain         X0 is [B][K][N]
//   1: concat        k<Csplit -> X0[B][Csplit][N] ; else scale1 * X1[B][K-Csplit][N]
//   2: im2col 3x3    X0 is [B][K/9][Hin][Win]; k -> (cin, tap), zero pad=1
//   3: sa-scaled     X0[B][K][N] * (1 + sa[B][N])   (fused spatial attention)
// Tiles: BM=BN=64, BK=8, 256 threads, 4x4 per-thread microtile.
// ---------------------------------------------------------------------------
template<int MODE>
__device__ __forceinline__ float loadX(const float* __restrict__ X0,
                                       const float* __restrict__ X1,
                                       const float* __restrict__ sa,
                                       int b, int k, int p,
                                       int K, int N, int Csplit, float scale1,
                                       int Hin, int Win)
{
    if (MODE == 0) {
        return X0[((size_t)b * K + k) * N + p];
    } else if (MODE == 1) {
        if (k < Csplit)
            return X0[((size_t)b * Csplit + k) * N + p];
        return scale1 * X1[((size_t)b * (K - Csplit) + (k - Csplit)) * N + p];
    } else if (MODE == 2) {
        int cin = k / 9;
        int t   = k - cin * 9;
        int hh  = p / Win + (t / 3) - 1;
        int ww  = (p - (p / Win) * Win) + (t - (t / 3) * 3) - 1;
        if ((unsigned)hh < (unsigned)Hin && (unsigned)ww < (unsigned)Win)
            return X0[(((size_t)b * (K / 9) + cin) * Hin + hh) * Win + ww];
        return 0.f;
    } else { // MODE 3
        return X0[((size_t)b * K + k) * N + p] * (1.f + sa[(size_t)b * N + p]);
    }
}

template<int MODE>
__global__ __launch_bounds__(256)
void gemm_kernel(const float* __restrict__ Wt,
                 const float* __restrict__ X0,
                 const float* __restrict__ X1,
                 const float* __restrict__ bias,
                 const float* __restrict__ sa,
                 float* __restrict__ out,
                 int M, int K, int N, int Csplit, float scale1,
                 int Hin, int Win, int relu)
{
    __shared__ float As[8][64];   // As[kk][m]
    __shared__ float Xs[8][64];   // Xs[kk][n]

    const int n0 = blockIdx.x * 64;
    const int m0 = blockIdx.y * 64;
    const int b  = blockIdx.z;
    const int tid = threadIdx.x;
    const int tx = tid & 15;        // N direction
    const int ty = tid >> 4;        // M direction

    float acc[4][4];
#pragma unroll
    for (int i = 0; i < 4; i++)
#pragma unroll
        for (int j = 0; j < 4; j++) acc[i][j] = 0.f;

    for (int k0 = 0; k0 < K; k0 += 8) {
        // load W tile (64 rows x 8 k), guard M edge (M=216 case)
        {
            int i = tid;
#pragma unroll
            for (int r = 0; r < 2; r++, i += 256) {
                int m = i >> 3, kk = i & 7;
                int row = m0 + m;
                As[kk][m] = (row < M) ? Wt[(size_t)row * K + (k0 + kk)] : 0.f;
            }
        }
        // load X tile (8 k x 64 n)
        {
            int i = tid;
#pragma unroll
            for (int r = 0; r < 2; r++, i += 256) {
                int kk = i >> 6, n = i & 63;
                Xs[kk][n] = loadX<MODE>(X0, X1, sa, b, k0 + kk, n0 + n,
                                        K, N, Csplit, scale1, Hin, Win);
            }
        }
        __syncthreads();

#pragma unroll
        for (int kk = 0; kk < 8; kk++) {
            float4 av = *reinterpret_cast<const float4*>(&As[kk][ty * 4]);
            float4 xv = *reinterpret_cast<const float4*>(&Xs[kk][tx * 4]);
            float a[4] = {av.x, av.y, av.z, av.w};
            float x[4] = {xv.x, xv.y, xv.z, xv.w};
#pragma unroll
            for (int i = 0; i < 4; i++)
#pragma unroll
                for (int j = 0; j < 4; j++)
                    acc[i][j] += a[i] * x[j];
        }
        __syncthreads();
    }

#pragma unroll
    for (int i = 0; i < 4; i++) {
        int row = m0 + ty * 4 + i;
        if (row >= M) continue;
        float bv = bias ? bias[row] : 0.f;
#pragma unroll
        for (int j = 0; j < 4; j++) {
            float v = acc[i][j] + bv;
            if (relu) v = fmaxf(v, 0.f);
            out[((size_t)b * M + row) * N + (n0 + tx * 4 + j)] = v;
        }
    }
}

// ---------------------------------------------------------------------------
// DCNv2 sampling: build im2col buffer col[b][(cin*9+k)][h*W+w] with modulated
// bilinear sampling (zero padding outside). One thread per (b, g, k, h, w),
// inner loop over the group's 32 channels reusing corner weights/indices.
// om layout [B][216][HW]: off_y = ch (g*9+k), off_x = ch 72+g*9+k,
// mask = sigmoid(ch 144+g*9+k).
// ---------------------------------------------------------------------------
__global__ __launch_bounds__(256)
void dcn_sample_kernel(const float* __restrict__ x,
                       const float* __restrict__ om,
                       float* __restrict__ col,
                       int H, int W)
{
    const int HW = H * W;
    const int total = NB * 72 * HW;
    int idx = blockIdx.x * blockDim.x + threadIdx.x;
    if (idx >= total) return;

    int p  = idx % HW;
    int gk = (idx / HW) % 72;
    int b  = idx / (72 * HW);
    int g  = gk / 9, k = gk - g * 9;
    int h  = p / W, w = p - h * W;

    float offy = om[((size_t)b * 216 +        gk) * HW + p];
    float offx = om[((size_t)b * 216 +  72 +  gk) * HW + p];
    float mraw = om[((size_t)b * 216 + 144 +  gk) * HW + p];
    float msk  = 1.f / (1.f + expf(-mraw));

    float yy = (float)h + (float)(k / 3 - 1) + offy;
    float xx = (float)w + (float)(k % 3 - 1) + offx;
    // safety clamp to keep int conversion defined for pathological offsets
    yy = fminf(fmaxf(yy, -1.0e6f), 1.0e6f);
    xx = fminf(fmaxf(xx, -1.0e6f), 1.0e6f);

    float y0f = floorf(yy), x0f = floorf(xx);
    int y0 = (int)y0f, x0 = (int)x0f;
    float fy = yy - y0f, fx = xx - x0f;

    bool vy0 = (y0 >= 0) && (y0 < H);
    bool vy1 = (y0 + 1 >= 0) && (y0 + 1 < H);
    bool vx0 = (x0 >= 0) && (x0 < W);
    bool vx1 = (x0 + 1 >= 0) && (x0 + 1 < W);

    int cy0 = min(max(y0, 0), H - 1);
    int cy1 = min(max(y0 + 1, 0), H - 1);
    int cx0 = min(max(x0, 0), W - 1);
    int cx1 = min(max(x0 + 1, 0), W - 1);

    float w00 = (vy0 && vx0) ? (1.f - fy) * (1.f - fx) * msk : 0.f;
    float w01 = (vy0 && vx1) ? (1.f - fy) * fx * msk : 0.f;
    float w10 = (vy1 && vx0) ? fy * (1.f - fx) * msk : 0.f;
    float w11 = (vy1 && vx1) ? fy * fx * msk : 0.f;

    int i00 = cy0 * W + cx0, i01 = cy0 * W + cx1;
    int i10 = cy1 * W + cx0, i11 = cy1 * W + cx1;

    const float* xb = x + (size_t)(b * 256 + g * 32) * HW;
    float* cb = col + ((size_t)b * 2304 + (size_t)(g * 32) * 9 + k) * HW + p;

#pragma unroll 4
    for (int c = 0; c < 32; c++) {
        const float* xc = xb + (size_t)c * HW;
        float v = w00 * xc[i00] + w01 * xc[i01] + w10 * xc[i10] + w11 * xc[i11];
        cb[(size_t)c * 9 * HW] = v;
    }
}

// ---------------------------------------------------------------------------
// Channel mean + max over 512 channels at 128x128 (sem front-end).
// ---------------------------------------------------------------------------
__global__ __launch_bounds__(256)
void meanmax_kernel(const float* __restrict__ f2, float* __restrict__ mm)
{
    int p = blockIdx.x * blockDim.x + threadIdx.x;   // 0..16383
    int b = blockIdx.y;
    if (p >= 16384) return;
    const float* base = f2 + (size_t)b * 512 * 16384 + p;
    float s = 0.f, mx = -3.402823466e38f;
    for (int c = 0; c < 512; c++) {
        float v = base[(size_t)c * 16384];
        s += v;
        mx = fmaxf(mx, v);
    }
    mm[((size_t)b * 2 + 0) * 16384 + p] = s * (1.f / 512.f);
    mm[((size_t)b * 2 + 1) * 16384 + p] = mx;
}

// ---------------------------------------------------------------------------
// 7x7 conv (2 -> 1, pad 3) + BatchNorm (inference) + sigmoid -> sa[b][p]
// ---------------------------------------------------------------------------
__global__ __launch_bounds__(256)
void sa_kernel(const float* __restrict__ mm, const float* __restrict__ wsa,
               const float* __restrict__ bng, const float* __restrict__ bnb,
               const float* __restrict__ bnm, const float* __restrict__ bnv,
               float* __restrict__ sa)
{
    int p = blockIdx.x * blockDim.x + threadIdx.x;
    int b = blockIdx.y;
    if (p >= 16384) return;
    int y = p >> 7, x = p & 127;
    float acc = 0.f;
#pragma unroll
    for (int ic = 0; ic < 2; ic++) {
        const float* src = mm + ((size_t)b * 2 + ic) * 16384;
        const float* wk = wsa + ic * 49;
#pragma unroll
        for (int ky = 0; ky < 7; ky++) {
            int yy = y + ky - 3;
            if ((unsigned)yy >= 128u) continue;
#pragma unroll
            for (int kx = 0; kx < 7; kx++) {
                int xx = x + kx - 3;
                if ((unsigned)xx >= 128u) continue;
                acc += src[yy * 128 + xx] * wk[ky * 7 + kx];
            }
        }
    }
    float a = (acc - bnm[0]) * rsqrtf(bnv[0] + 1e-5f) * bng[0] + bnb[0];
    sa[(size_t)b * 16384 + p] = 1.f / (1.f + expf(-a));
}

// ---------------------------------------------------------------------------
// GroupNorm (32 groups over C=256, HW=16384). Reduce then apply.
// ---------------------------------------------------------------------------
__global__ __launch_bounds__(256)
void gn_reduce_kernel(const float* __restrict__ y, float* __restrict__ stats)
{
    const int bg = blockIdx.x;                 // b*32+g, 0..127
    const float* base = y + (size_t)bg * 8 * 16384;   // 8 channels/group, contiguous
    float s = 0.f, sq = 0.f;
    for (int i = threadIdx.x; i < 8 * 16384; i += 256) {
        float v = base[i];
        s += v;
        sq += v * v;
    }
    __shared__ float ss[256], ssq[256];
    ss[threadIdx.x] = s;
    ssq[threadIdx.x] = sq;
    __syncthreads();
    for (int st = 128; st > 0; st >>= 1) {
        if (threadIdx.x < st) {
            ss[threadIdx.x]  += ss[threadIdx.x + st];
            ssq[threadIdx.x] += ssq[threadIdx.x + st];
        }
        __syncthreads();
    }
    if (threadIdx.x == 0) {
        const float inv = 1.f / (8.f * 16384.f);
        float mean = ss[0] * inv;
        float var  = ssq[0] * inv - mean * mean;
        stats[bg * 2 + 0] = mean;
        stats[bg * 2 + 1] = rsqrtf(var + 1e-5f);
    }
}

__global__ __launch_bounds__(256)
void gn_apply_kernel(const float* __restrict__ y, const float* __restrict__ stats,
                     const float* __restrict__ gg, const float* __restrict__ gb,
                     float* __restrict__ out)
{
    size_t idx = (size_t)blockIdx.x * blockDim.x + threadIdx.x;
    if (idx >= (size_t)16777216) return;
    int c = (int)((idx >> 14) & 255);
    int b = (int)(idx >> 22);
    int g = c >> 3;
    float mean = stats[(b * 32 + g) * 2 + 0];
    float rstd = stats[(b * 32 + g) * 2 + 1];
    out[idx] = (y[idx] - mean) * rstd * gg[c] + gb[c];
}

// ---------------------------------------------------------------------------
// Host orchestration
// ---------------------------------------------------------------------------
static void* symaddr(const void* sym)
{
    void* p = nullptr;
    cudaGetSymbolAddress(&p, sym);
    return p;
}

extern "C" void kernel_launch(void* const* d_in, const int* in_sizes, int n_in,
                              void* d_out, int out_size)
{
    (void)in_sizes; (void)n_in; (void)out_size;

    const float* feat_3 = (const float*)d_in[1];
    const float* feat_4 = (const float*)d_in[2];
    const float* feat_5 = (const float*)d_in[3];
    const float* w_off5 = (const float*)d_in[4];
    const float* w_om5  = (const float*)d_in[5];
    const float* b_om5  = (const float*)d_in[6];
    const float* w_dcn5 = (const float*)d_in[7];
    const float* b_dcn5 = (const float*)d_in[8];
    const float* w_c1   = (const float*)d_in[9];
    const float* w_off4 = (const float*)d_in[10];
    const float* w_om4  = (const float*)d_in[11];
    const float* b_om4  = (const float*)d_in[12];
    const float* w_dcn4 = (const float*)d_in[13];
    const float* b_dcn4 = (const float*)d_in[14];
    const float* w_sa   = (const float*)d_in[15];
    const float* bn_g   = (const float*)d_in[16];
    const float* bn_b   = (const float*)d_in[17];
    const float* bn_m   = (const float*)d_in[18];
    const float* bn_v   = (const float*)d_in[19];
    const float* w_sem  = (const float*)d_in[20];
    const float* gn_g   = (const float*)d_in[21];
    const float* gn_b   = (const float*)d_in[22];
    float* out = (float*)d_out;

    float* up5  = (float*)symaddr(g_up5);
    float* off5 = (float*)symaddr(g_off5);
    float* om5  = (float*)symaddr(g_om5);
    float* col  = (float*)symaddr(g_col);
    float* al5  = (float*)symaddr(g_al5);
    float* c1b  = (float*)symaddr(g_c1b);
    float* up4  = (float*)symaddr(g_up4);
    float* off4 = (float*)symaddr(g_off4);
    float* om4  = (float*)symaddr(g_om4);
    float* al4  = (float*)symaddr(g_al4);
    float* f2   = (float*)symaddr(g_f2);
    float* mm   = (float*)symaddr(g_mm);
    float* sab  = (float*)symaddr(g_sab);
    float* ybuf = (float*)symaddr(g_y);
    float* st   = (float*)symaddr(g_st);

    // ----- level 5 (16 -> 32) ---------------------------------------------
    {
        long total = 4L * 256 * 32 * 32;
        upsample2x_kernel<<<(unsigned)((total + 255) / 256), 256>>>(
            feat_5, feat_5, 256, 256, 16, 16, up5);
    }
    // off5 = conv1x1(concat(feat_4, 2*feat_up5))
    gemm_kernel<1><<<dim3(1024 / 64, 4, NB), 256>>>(
        w_off5, feat_4, up5, nullptr, nullptr, off5,
        256, 512, 1024, 256, 2.0f, 0, 0, 0);
    // om5 = conv3x3(off5) + b_om5   (implicit im2col GEMM)
    gemm_kernel<2><<<dim3(1024 / 64, (216 + 63) / 64, NB), 256>>>(
        w_om5, off5, nullptr, b_om5, nullptr, om5,
        216, 2304, 1024, 0, 0.f, 32, 32, 0);
    // DCN sampling -> col
    {
        int total = NB * 72 * 1024;
        dcn_sample_kernel<<<(total + 255) / 256, 256>>>(up5, om5, col, 32, 32);
    }
    // feat_5_align = relu(W_dcn5 * col + b)
    gemm_kernel<0><<<dim3(1024 / 64, 4, NB), 256>>>(
        w_dcn5, col, nullptr, b_dcn5, nullptr, al5,
        256, 2304, 1024, 0, 0.f, 0, 0, 1);
    // feat_4' = conv1x1(concat(feat_5_align, feat_4))
    gemm_kernel<1><<<dim3(1024 / 64, 4, NB), 256>>>(
        w_c1, al5, feat_4, nullptr, nullptr, c1b,
        256, 512, 1024, 256, 1.0f, 0, 0, 0);

    // ----- level 4 (32 -> 64) ---------------------------------------------
    {
        long total = 4L * 256 * 64 * 64;
        upsample2x_kernel<<<(unsigned)((total + 255) / 256), 256>>>(
            c1b, c1b, 256, 256, 32, 32, up4);
    }
    gemm_kernel<1><<<dim3(4096 / 64, 4, NB), 256>>>(
        w_off4, feat_3, up4, nullptr, nullptr, off4,
        256, 512, 4096, 256, 2.0f, 0, 0, 0);
    gemm_kernel<2><<<dim3(4096 / 64, (216 + 63) / 64, NB), 256>>>(
        w_om4, off4, nullptr, b_om4, nullptr, om4,
        216, 2304, 4096, 0, 0.f, 64, 64, 0);
    {
        int total = NB * 72 * 4096;
        dcn_sample_kernel<<<(total + 255) / 256, 256>>>(up4, om4, col, 64, 64);
    }
    gemm_kernel<0><<<dim3(4096 / 64, 4, NB), 256>>>(
        w_dcn4, col, nullptr, b_dcn4, nullptr, al4,
        256, 2304, 4096, 0, 0.f, 0, 0, 1);

    // ----- feat_2 = resize(concat(feat_4_align, feat_3), 128x128) ----------
    {
        long total = 4L * 512 * 128 * 128;
        upsample2x_kernel<<<(unsigned)((total + 255) / 256), 256>>>(
            al4, feat_3, 256, 512, 64, 64, f2);
    }

    // ----- SEM --------------------------------------------------------------
    meanmax_kernel<<<dim3(16384 / 256, NB), 256>>>(f2, mm);
    sa_kernel<<<dim3(16384 / 256, NB), 256>>>(mm, w_sa, bn_g, bn_b, bn_m, bn_v, sab);
    // y = conv1x1( feat_2 * (1 + sa) )   [fused]
    gemm_kernel<3><<<dim3(16384 / 64, 4, NB), 256>>>(
        w_sem, f2, nullptr, nullptr, sab, ybuf,
        256, 512, 16384, 0, 0.f, 0, 0, 0);
    // GroupNorm
    gn_reduce_kernel<<<128, 256>>>(ybuf, st);
    gn_apply_kernel<<<16777216 / 256, 256>>>(ybuf, st, gn_g, gn_b, out);
}

// round 5
// speedup vs baseline: 1.2276x; 1.2276x over previous
#include <cuda_runtime.h>

// ---------------------------------------------------------------------------
// Problem constants (fixed shapes from setup_inputs)
//   B=4, C=256, levels: 16x16 -> 32x32 -> 64x64 -> 128x128, dg=8, Cpg=32
// ---------------------------------------------------------------------------
#define NB 4

// ------------------------- static scratch buffers --------------------------
static __device__ float g_up5 [4u * 256u * 32u * 32u];
static __device__ float g_off5[4u * 256u * 32u * 32u];
static __device__ float g_om5 [4u * 216u * 32u * 32u];
static __device__ float g_col [4u * 2304u * 64u * 64u];   // 151 MB (shared by both DCN levels)
static __device__ float g_al5 [4u * 256u * 32u * 32u];
static __device__ float g_c1b [4u * 256u * 32u * 32u];
static __device__ float g_up4 [4u * 256u * 64u * 64u];
static __device__ float g_off4[4u * 256u * 64u * 64u];
static __device__ float g_om4 [4u * 216u * 64u * 64u];
static __device__ float g_al4 [4u * 256u * 64u * 64u];
static __device__ float g_f2  [4u * 512u * 128u * 128u];
static __device__ float g_mm  [4u * 2u * 128u * 128u];
static __device__ float g_sab [4u * 128u * 128u];
static __device__ float g_y   [4u * 256u * 128u * 128u];
static __device__ float g_st  [256];

// ---------------------------------------------------------------------------
// Bilinear 2x upsample, half-pixel centers, clamp-to-edge.
// Dual source: channel c < Csplit reads src0, else src1 (fuses concat+resize).
// ---------------------------------------------------------------------------
__global__ __launch_bounds__(256)
void upsample2x_kernel(const float* __restrict__ src0,
                       const float* __restrict__ src1,
                       int Csplit, int C, int Hin, int Win,
                       float* __restrict__ dst)
{
    const int Hout = Hin * 2, Wout = Win * 2;
    const long total = (long)NB * C * Hout * Wout;
    long idx = (long)blockIdx.x * blockDim.x + threadIdx.x;
    if (idx >= total) return;
    int x = (int)(idx % Wout);
    int y = (int)((idx / Wout) % Hout);
    int c = (int)((idx / ((long)Wout * Hout)) % C);
    int b = (int)(idx / ((long)Wout * Hout * C));

    float sy = y * 0.5f - 0.25f;
    float sx = x * 0.5f - 0.25f;
    float y0f = floorf(sy), x0f = floorf(sx);
    float fy = sy - y0f, fx = sx - x0f;
    int y0 = (int)y0f, x0 = (int)x0f;
    int y0c = min(max(y0, 0), Hin - 1);
    int y1c = min(max(y0 + 1, 0), Hin - 1);
    int x0c = min(max(x0, 0), Win - 1);
    int x1c = min(max(x0 + 1, 0), Win - 1);

    const float* s = (c < Csplit)
        ? src0 + (size_t)(b * Csplit + c) * Hin * Win
        : src1 + (size_t)(b * (C - Csplit) + (c - Csplit)) * Hin * Win;

    float v00 = s[y0c * Win + x0c];
    float v01 = s[y0c * Win + x1c];
    float v10 = s[y1c * Win + x0c];
    float v11 = s[y1c * Win + x1c];
    dst[idx] = (1.f - fy) * ((1.f - fx) * v00 + fx * v01)
             +         fy * ((1.f - fx) * v10 + fx * v11);
}

// ---------------------------------------------------------------------------
// X loader modes (shared by GEMM):
//   0: plain         X0 is [B][K][N]
//   1: concat        k<Csplit -> X0[B][Csplit][N] ; else scale1 * X1[...]
//   2: im2col 3x3    X0 is [B][K/9][Hin][Win]; zero pad=1
//   3: sa-scaled     X0[B][K][N] * (1 + sa[B][N])
// ---------------------------------------------------------------------------
template<int MODE>
__device__ __forceinline__ float loadX(const float* __restrict__ X0,
                                       const float* __restrict__ X1,
                                       const float* __restrict__ sa,
                                       int b, int k, int p,
                                       int K, int N, int Csplit, float scale1,
                                       int Hin, int Win)
{
    if (MODE == 0) {
        return X0[((size_t)b * K + k) * N + p];
    } else if (MODE == 1) {
        if (k < Csplit)
            return X0[((size_t)b * Csplit + k) * N + p];
        return scale1 * X1[((size_t)b * (K - Csplit) + (k - Csplit)) * N + p];
    } else if (MODE == 2) {
        int cin = k / 9;
        int t   = k - cin * 9;
        int hh  = p / Win + (t / 3) - 1;
        int ww  = (p - (p / Win) * Win) + (t - (t / 3) * 3) - 1;
        if ((unsigned)hh < (unsigned)Hin && (unsigned)ww < (unsigned)Win)
            return X0[(((size_t)b * (K / 9) + cin) * Hin + hh) * Win + ww];
        return 0.f;
    } else { // MODE 3
        return X0[((size_t)b * K + k) * N + p] * (1.f + sa[(size_t)b * N + p]);
    }
}

// ---------------------------------------------------------------------------
// Packed-f32x2 GEMM: out[b, m, p] = act( sum_k W[m,k] * X(b,k,p) + bias[m] )
// BM=128, BN = 64 or 128, BK=16, 256 threads, microtile 8 x (BN/16).
// Uses SASS FFMA2 via PTX fma.rn.f32x2 (2x fp32 FMA throughput).
//  - A stored DUPLICATED in SMEM ((a,a) per element): one broadcast LDS.128
//    yields two 64-bit duplicated A operands -> no packing MOVs.
//  - X pairs come naturally from a conflict-free LDS.128 of plain Xs.
// ---------------------------------------------------------------------------
#define FMA2(c, a, b) asm("fma.rn.f32x2 %0, %1, %2, %0;" : "+l"(c) : "l"(a), "l"(b))

union F4U {
    float4 f;
    unsigned long long u[2];
    float s[4];
};

template<int MODE, int BN>
__global__ __launch_bounds__(256, 2)
void gemm2_kernel(const float* __restrict__ Wt,
                  const float* __restrict__ X0,
                  const float* __restrict__ X1,
                  const float* __restrict__ bias,
                  const float* __restrict__ sa,
                  float* __restrict__ out,
                  int M, int K, int N, int Csplit, float scale1,
                  int Hin, int Win, int relu)
{
    constexpr int AS_STRIDE = 260;          // 128*2 + 4 pad (keeps 16B align, spreads banks)
    constexpr int NJ = BN / 64;             // float4 X loads per kk (1 or 2)
    __shared__ __align__(16) float As2[16 * AS_STRIDE];
    __shared__ __align__(16) float Xs[16 * BN];

    const int n0  = blockIdx.x * BN;
    const int m0  = blockIdx.y * 128;
    const int b   = blockIdx.z;
    const int tid = threadIdx.x;
    const int tx  = tid & 15;               // n quad
    const int ty  = tid >> 4;               // m oct

    unsigned long long acc[8][2 * NJ];
#pragma unroll
    for (int i = 0; i < 8; i++)
#pragma unroll
        for (int j = 0; j < 2 * NJ; j++) acc[i][j] = 0ull;  // packed (0.f, 0.f)

    for (int k0 = 0; k0 < K; k0 += 16) {
        // ---- fill A tile (128 m x 16 k), duplicated, coalesced W reads ----
#pragma unroll
        for (int r = 0; r < 8; r++) {
            int i = tid + r * 256;
            int kk = i & 15, m = i >> 4;
            int row = m0 + m;
            float v = (row < M) ? Wt[(size_t)row * K + (k0 + kk)] : 0.f;
            *reinterpret_cast<float2*>(&As2[kk * AS_STRIDE + m * 2]) = make_float2(v, v);
        }
        // ---- fill X tile (16 k x BN n) ----
#pragma unroll
        for (int r = 0; r < (16 * BN) / 256; r++) {
            int i = tid + r * 256;
            int n = i & (BN - 1), kk = i / BN;
            Xs[kk * BN + n] = loadX<MODE>(X0, X1, sa, b, k0 + kk, n0 + n,
                                          K, N, Csplit, scale1, Hin, Win);
        }
        __syncthreads();

#pragma unroll
        for (int kk = 0; kk < 16; kk++) {
            unsigned long long xv[2 * NJ];
#pragma unroll
            for (int j = 0; j < NJ; j++) {
                F4U xu;
                xu.f = *reinterpret_cast<const float4*>(&Xs[kk * BN + j * 64 + tx * 4]);
                xv[2 * j]     = xu.u[0];
                xv[2 * j + 1] = xu.u[1];
            }
#pragma unroll
            for (int i2 = 0; i2 < 4; i2++) {
                F4U au;   // two duplicated A operands: (a[2i2],a[2i2]), (a[2i2+1],a[2i2+1])
                au.f = *reinterpret_cast<const float4*>(
                           &As2[kk * AS_STRIDE + (ty * 8 + i2 * 2) * 2]);
#pragma unroll
                for (int jj = 0; jj < 2 * NJ; jj++) {
                    FMA2(acc[i2 * 2][jj],     au.u[0], xv[jj]);
                    FMA2(acc[i2 * 2 + 1][jj], au.u[1], xv[jj]);
                }
            }
        }
        __syncthreads();
    }

    // ---- epilogue: bias + optional relu, float4 stores ----
#pragma unroll
    for (int i = 0; i < 8; i++) {
        int row = m0 + ty * 8 + i;
        if (row >= M) continue;
        float bv = bias ? bias[row] : 0.f;
#pragma unroll
        for (int j = 0; j < NJ; j++) {
            F4U o;
            o.u[0] = acc[i][2 * j];
            o.u[1] = acc[i][2 * j + 1];
#pragma unroll
            for (int q = 0; q < 4; q++) {
                float v = o.s[q] + bv;
                if (relu) v = fmaxf(v, 0.f);
                o.s[q] = v;
            }
            *reinterpret_cast<float4*>(
                &out[((size_t)b * M + row) * N + n0 + j * 64 + tx * 4]) = o.f;
        }
    }
}

// ---------------------------------------------------------------------------
// DCNv2 sampling -> im2col buffer col[b][(cin*9+k)][p], modulated bilinear,
// zero padding. One thread per (b,g,k,h,w); loops the group's 32 channels.
// ---------------------------------------------------------------------------
__global__ __launch_bounds__(256)
void dcn_sample_kernel(const float* __restrict__ x,
                       const float* __restrict__ om,
                       float* __restrict__ col,
                       int H, int W)
{
    const int HW = H * W;
    const int total = NB * 72 * HW;
    int idx = blockIdx.x * blockDim.x + threadIdx.x;
    if (idx >= total) return;

    int p  = idx % HW;
    int gk = (idx / HW) % 72;
    int b  = idx / (72 * HW);
    int g  = gk / 9, k = gk - g * 9;
    int h  = p / W, w = p - h * W;

    float offy = om[((size_t)b * 216 +        gk) * HW + p];
    float offx = om[((size_t)b * 216 +  72 +  gk) * HW + p];
    float mraw = om[((size_t)b * 216 + 144 +  gk) * HW + p];
    float msk  = 1.f / (1.f + expf(-mraw));

    float yy = (float)h + (float)(k / 3 - 1) + offy;
    float xx = (float)w + (float)(k % 3 - 1) + offx;
    yy = fminf(fmaxf(yy, -1.0e6f), 1.0e6f);
    xx = fminf(fmaxf(xx, -1.0e6f), 1.0e6f);

    float y0f = floorf(yy), x0f = floorf(xx);
    int y0 = (int)y0f, x0 = (int)x0f;
    float fy = yy - y0f, fx = xx - x0f;

    bool vy0 = (y0 >= 0) && (y0 < H);
    bool vy1 = (y0 + 1 >= 0) && (y0 + 1 < H);
    bool vx0 = (x0 >= 0) && (x0 < W);
    bool vx1 = (x0 + 1 >= 0) && (x0 + 1 < W);

    int cy0 = min(max(y0, 0), H - 1);
    int cy1 = min(max(y0 + 1, 0), H - 1);
    int cx0 = min(max(x0, 0), W - 1);
    int cx1 = min(max(x0 + 1, 0), W - 1);

    float w00 = (vy0 && vx0) ? (1.f - fy) * (1.f - fx) * msk : 0.f;
    float w01 = (vy0 && vx1) ? (1.f - fy) * fx * msk : 0.f;
    float w10 = (vy1 && vx0) ? fy * (1.f - fx) * msk : 0.f;
    float w11 = (vy1 && vx1) ? fy * fx * msk : 0.f;

    int i00 = cy0 * W + cx0, i01 = cy0 * W + cx1;
    int i10 = cy1 * W + cx0, i11 = cy1 * W + cx1;

    const float* xb = x + (size_t)(b * 256 + g * 32) * HW;
    float* cb = col + ((size_t)b * 2304 + (size_t)(g * 32) * 9 + k) * HW + p;

#pragma unroll 4
    for (int c = 0; c < 32; c++) {
        const float* xc = xb + (size_t)c * HW;
        float v = w00 * xc[i00] + w01 * xc[i01] + w10 * xc[i10] + w11 * xc[i11];
        cb[(size_t)c * 9 * HW] = v;
    }
}

// ---------------------------------------------------------------------------
// Channel mean + max over 512 channels at 128x128 (sem front-end).
// ---------------------------------------------------------------------------
__global__ __launch_bounds__(256)
void meanmax_kernel(const float* __restrict__ f2, float* __restrict__ mm)
{
    int p = blockIdx.x * blockDim.x + threadIdx.x;
    int b = blockIdx.y;
    if (p >= 16384) return;
    const float* base = f2 + (size_t)b * 512 * 16384 + p;
    float s = 0.f, mx = -3.402823466e38f;
    for (int c = 0; c < 512; c++) {
        float v = base[(size_t)c * 16384];
        s += v;
        mx = fmaxf(mx, v);
    }
    mm[((size_t)b * 2 + 0) * 16384 + p] = s * (1.f / 512.f);
    mm[((size_t)b * 2 + 1) * 16384 + p] = mx;
}

// ---------------------------------------------------------------------------
// 7x7 conv (2 -> 1, pad 3) + BatchNorm (inference) + sigmoid -> sa[b][p]
// ---------------------------------------------------------------------------
__global__ __launch_bounds__(256)
void sa_kernel(const float* __restrict__ mm, const float* __restrict__ wsa,
               const float* __restrict__ bng, const float* __restrict__ bnb,
               const float* __restrict__ bnm, const float* __restrict__ bnv,
               float* __restrict__ sa)
{
    int p = blockIdx.x * blockDim.x + threadIdx.x;
    int b = blockIdx.y;
    if (p >= 16384) return;
    int y = p >> 7, x = p & 127;
    float acc = 0.f;
#pragma unroll
    for (int ic = 0; ic < 2; ic++) {
        const float* src = mm + ((size_t)b * 2 + ic) * 16384;
        const float* wk = wsa + ic * 49;
#pragma unroll
        for (int ky = 0; ky < 7; ky++) {
            int yy = y + ky - 3;
            if ((unsigned)yy >= 128u) continue;
#pragma unroll
            for (int kx = 0; kx < 7; kx++) {
                int xx = x + kx - 3;
                if ((unsigned)xx >= 128u) continue;
                acc += src[yy * 128 + xx] * wk[ky * 7 + kx];
            }
        }
    }
    float a = (acc - bnm[0]) * rsqrtf(bnv[0] + 1e-5f) * bng[0] + bnb[0];
    sa[(size_t)b * 16384 + p] = 1.f / (1.f + expf(-a));
}

// ---------------------------------------------------------------------------
// GroupNorm (32 groups over C=256, HW=16384). Reduce then apply.
// ---------------------------------------------------------------------------
__global__ __launch_bounds__(256)
void gn_reduce_kernel(const float* __restrict__ y, float* __restrict__ stats)
{
    const int bg = blockIdx.x;
    const float* base = y + (size_t)bg * 8 * 16384;
    float s = 0.f, sq = 0.f;
    for (int i = threadIdx.x; i < 8 * 16384; i += 256) {
        float v = base[i];
        s += v;
        sq += v * v;
    }
    __shared__ float ss[256], ssq[256];
    ss[threadIdx.x] = s;
    ssq[threadIdx.x] = sq;
    __syncthreads();
    for (int st = 128; st > 0; st >>= 1) {
        if (threadIdx.x < st) {
            ss[threadIdx.x]  += ss[threadIdx.x + st];
            ssq[threadIdx.x] += ssq[threadIdx.x + st];
        }
        __syncthreads();
    }
    if (threadIdx.x == 0) {
        const float inv = 1.f / (8.f * 16384.f);
        float mean = ss[0] * inv;
        float var  = ssq[0] * inv - mean * mean;
        stats[bg * 2 + 0] = mean;
        stats[bg * 2 + 1] = rsqrtf(var + 1e-5f);
    }
}

__global__ __launch_bounds__(256)
void gn_apply_kernel(const float* __restrict__ y, const float* __restrict__ stats,
                     const float* __restrict__ gg, const float* __restrict__ gb,
                     float* __restrict__ out)
{
    size_t idx = (size_t)blockIdx.x * blockDim.x + threadIdx.x;
    if (idx >= (size_t)16777216) return;
    int c = (int)((idx >> 14) & 255);
    int b = (int)(idx >> 22);
    int g = c >> 3;
    float mean = stats[(b * 32 + g) * 2 + 0];
    float rstd = stats[(b * 32 + g) * 2 + 1];
    out[idx] = (y[idx] - mean) * rstd * gg[c] + gb[c];
}

// ---------------------------------------------------------------------------
// Host orchestration
// ---------------------------------------------------------------------------
static void* symaddr(const void* sym)
{
    void* p = nullptr;
    cudaGetSymbolAddress(&p, sym);
    return p;
}

extern "C" void kernel_launch(void* const* d_in, const int* in_sizes, int n_in,
                              void* d_out, int out_size)
{
    (void)in_sizes; (void)n_in; (void)out_size;

    const float* feat_3 = (const float*)d_in[1];
    const float* feat_4 = (const float*)d_in[2];
    const float* feat_5 = (const float*)d_in[3];
    const float* w_off5 = (const float*)d_in[4];
    const float* w_om5  = (const float*)d_in[5];
    const float* b_om5  = (const float*)d_in[6];
    const float* w_dcn5 = (const float*)d_in[7];
    const float* b_dcn5 = (const float*)d_in[8];
    const float* w_c1   = (const float*)d_in[9];
    const float* w_off4 = (const float*)d_in[10];
    const float* w_om4  = (const float*)d_in[11];
    const float* b_om4  = (const float*)d_in[12];
    const float* w_dcn4 = (const float*)d_in[13];
    const float* b_dcn4 = (const float*)d_in[14];
    const float* w_sa   = (const float*)d_in[15];
    const float* bn_g   = (const float*)d_in[16];
    const float* bn_b   = (const float*)d_in[17];
    const float* bn_m   = (const float*)d_in[18];
    const float* bn_v   = (const float*)d_in[19];
    const float* w_sem  = (const float*)d_in[20];
    const float* gn_g   = (const float*)d_in[21];
    const float* gn_b   = (const float*)d_in[22];
    float* out = (float*)d_out;

    float* up5  = (float*)symaddr(g_up5);
    float* off5 = (float*)symaddr(g_off5);
    float* om5  = (float*)symaddr(g_om5);
    float* col  = (float*)symaddr(g_col);
    float* al5  = (float*)symaddr(g_al5);
    float* c1b  = (float*)symaddr(g_c1b);
    float* up4  = (float*)symaddr(g_up4);
    float* off4 = (float*)symaddr(g_off4);
    float* om4  = (float*)symaddr(g_om4);
    float* al4  = (float*)symaddr(g_al4);
    float* f2   = (float*)symaddr(g_f2);
    float* mm   = (float*)symaddr(g_mm);
    float* sab  = (float*)symaddr(g_sab);
    float* ybuf = (float*)symaddr(g_y);
    float* st   = (float*)symaddr(g_st);

    // ----- level 5 (16 -> 32), N=1024: BN=64 to fill the chip ---------------
    {
        long total = 4L * 256 * 32 * 32;
        upsample2x_kernel<<<(unsigned)((total + 255) / 256), 256>>>(
            feat_5, feat_5, 256, 256, 16, 16, up5);
    }
    // off5 = conv1x1(concat(feat_4, 2*feat_up5))
    gemm2_kernel<1, 64><<<dim3(1024 / 64, 2, NB), 256>>>(
        w_off5, feat_4, up5, nullptr, nullptr, off5,
        256, 512, 1024, 256, 2.0f, 0, 0, 0);
    // om5 = conv3x3(off5) + b_om5   (implicit im2col GEMM)
    gemm2_kernel<2, 64><<<dim3(1024 / 64, 2, NB), 256>>>(
        w_om5, off5, nullptr, b_om5, nullptr, om5,
        216, 2304, 1024, 0, 0.f, 32, 32, 0);
    // DCN sampling -> col
    {
        int total = NB * 72 * 1024;
        dcn_sample_kernel<<<(total + 255) / 256, 256>>>(up5, om5, col, 32, 32);
    }
    // feat_5_align = relu(W_dcn5 * col + b)
    gemm2_kernel<0, 64><<<dim3(1024 / 64, 2, NB), 256>>>(
        w_dcn5, col, nullptr, b_dcn5, nullptr, al5,
        256, 2304, 1024, 0, 0.f, 0, 0, 1);
    // feat_4' = conv1x1(concat(feat_5_align, feat_4))
    gemm2_kernel<1, 64><<<dim3(1024 / 64, 2, NB), 256>>>(
        w_c1, al5, feat_4, nullptr, nullptr, c1b,
        256, 512, 1024, 256, 1.0f, 0, 0, 0);

    // ----- level 4 (32 -> 64), N=4096: BN=128 --------------------------------
    {
        long total = 4L * 256 * 64 * 64;
        upsample2x_kernel<<<(unsigned)((total + 255) / 256), 256>>>(
            c1b, c1b, 256, 256, 32, 32, up4);
    }
    gemm2_kernel<1, 128><<<dim3(4096 / 128, 2, NB), 256>>>(
        w_off4, feat_3, up4, nullptr, nullptr, off4,
        256, 512, 4096, 256, 2.0f, 0, 0, 0);
    gemm2_kernel<2, 128><<<dim3(4096 / 128, 2, NB), 256>>>(
        w_om4, off4, nullptr, b_om4, nullptr, om4,
        216, 2304, 4096, 0, 0.f, 64, 64, 0);
    {
        int total = NB * 72 * 4096;
        dcn_sample_kernel<<<(total + 255) / 256, 256>>>(up4, om4, col, 64, 64);
    }
    gemm2_kernel<0, 128><<<dim3(4096 / 128, 2, NB), 256>>>(
        w_dcn4, col, nullptr, b_dcn4, nullptr, al4,
        256, 2304, 4096, 0, 0.f, 0, 0, 1);

    // ----- feat_2 = resize(concat(feat_4_align, feat_3), 128x128) ------------
    {
        long total = 4L * 512 * 128 * 128;
        upsample2x_kernel<<<(unsigned)((total + 255) / 256), 256>>>(
            al4, feat_3, 256, 512, 64, 64, f2);
    }

    // ----- SEM ---------------------------------------------------------------
    meanmax_kernel<<<dim3(16384 / 256, NB), 256>>>(f2, mm);
    sa_kernel<<<dim3(16384 / 256, NB), 256>>>(mm, w_sa, bn_g, bn_b, bn_m, bn_v, sab);
    // y = conv1x1( feat_2 * (1 + sa) )   [fused spatial attention]
    gemm2_kernel<3, 128><<<dim3(16384 / 128, 2, NB), 256>>>(
        w_sem, f2, nullptr, nullptr, sab, ybuf,
        256, 512, 16384, 0, 0.f, 0, 0, 0);
    // GroupNorm
    gn_reduce_kernel<<<128, 256>>>(ybuf, st);
    gn_apply_kernel<<<16777216 / 256, 256>>>(ybuf, st, gn_g, gn_b, out);
}